// round 3
// baseline (speedup 1.0000x reference)
#include <cuda_runtime.h>

// ---------------- problem constants ----------------
#define BB    64    // batch
#define NNv   64    // news per batch
#define HLv   50    // history length
#define INv   384   // input dim
#define POSv  64    // pos-emb dim
#define ATTv  256   // attention hidden dim
#define NEWSv 448   // IN + POS
#define W1LD  896   // W1 row stride (2*NEWS)

// ---------------- device scratch (no allocations allowed) ----------------
__device__ float g_PN[BB * NNv * ATTv];    // 4 MB  : pn + t0   [4096, 256]
__device__ float g_PL[BB * HLv * ATTv];    // 3.3 MB: pl + posW [3200, 256]
__device__ float g_t0[ATTv];               // b1 + pos0 @ Wn_pos
__device__ float g_posW[HLv * ATTv];       // pos_emb[1+h] @ Wl_pos

__device__ __forceinline__ float tanh_fast(float x) {
    float y;
    asm("tanh.approx.f32 %0, %1;" : "=f"(y) : "f"(x));
    return y;
}

// ---------------- K0: tiny precompute of t0 and posW ----------------
__global__ void prep_kernel(const float* __restrict__ pos_emb,
                            const float* __restrict__ W1,
                            const float* __restrict__ b1) {
    int a = threadIdx.x;  // 0..255
    if (blockIdx.x == 0) {
        float s = b1[a];
#pragma unroll
        for (int j = 0; j < POSv; j++)
            s += pos_emb[j] * W1[a * W1LD + INv + j];
        g_t0[a] = s;
    } else {
        int h = blockIdx.x - 1;  // 0..49
        float s = 0.f;
#pragma unroll
        for (int j = 0; j < POSv; j++)
            s += pos_emb[(1 + h) * POSv + j] * W1[a * W1LD + NEWSv + INv + j];
        g_posW[h * ATTv + a] = s;
    }
}

// ---------------- K1: nf output (pure copy/broadcast) ----------------
__global__ void nf_kernel(const float* __restrict__ news,
                          const float* __restrict__ pos_emb,
                          float* __restrict__ out_nf) {
    int bn = blockIdx.x;      // 0..4095
    int d  = threadIdx.x;     // 0..447
    float v = (d < INv) ? news[bn * INv + d] : pos_emb[d - INv];
    out_nf[bn * NEWSv + d] = v;
}

// ---------------- K2: fused FFMA GEMMs  (z=0: PN, z=1: PL) ----------------
// C[m,a] = sum_k A[m,k] * W1[a, colofs+k]  + bias
// Tiles: BM=BN=64, BK=16, 256 threads, 4x4 register blocking.
__global__ __launch_bounds__(256) void gemm_kernel(const float* __restrict__ news,
                                                   const float* __restrict__ logv,
                                                   const float* __restrict__ W1) {
    const int isPL = blockIdx.z;
    const float* A;
    float* C;
    int colofs;
    if (isPL) {
        if (blockIdx.y >= 50) return;  // PL has only 3200/64 = 50 row-blocks
        A = logv; C = g_PL; colofs = NEWSv;
    } else {
        A = news; C = g_PN; colofs = 0;
    }
    const int m0 = blockIdx.y * 64;
    const int n0 = blockIdx.x * 64;

    __shared__ __align__(16) float As[16][68];  // transposed: As[k][m]
    __shared__ __align__(16) float Bs[16][68];  // transposed: Bs[k][a]

    const int tid = threadIdx.x;
    const int tx = tid & 15, ty = tid >> 4;
    const int lr = tid >> 2, lc = tid & 3;   // loader: row, 4-float col group

    float acc[4][4];
#pragma unroll
    for (int i = 0; i < 4; i++)
#pragma unroll
        for (int j = 0; j < 4; j++) acc[i][j] = 0.f;

    const float* Aptr = A  + (m0 + lr) * INv  + lc * 4;
    const float* Bptr = W1 + (n0 + lr) * W1LD + colofs + lc * 4;

    for (int k0 = 0; k0 < INv; k0 += 16) {
        float4 av = *(const float4*)(Aptr + k0);
        float4 bv = *(const float4*)(Bptr + k0);
        As[lc * 4 + 0][lr] = av.x; As[lc * 4 + 1][lr] = av.y;
        As[lc * 4 + 2][lr] = av.z; As[lc * 4 + 3][lr] = av.w;
        Bs[lc * 4 + 0][lr] = bv.x; Bs[lc * 4 + 1][lr] = bv.y;
        Bs[lc * 4 + 2][lr] = bv.z; Bs[lc * 4 + 3][lr] = bv.w;
        __syncthreads();
#pragma unroll
        for (int k = 0; k < 16; k++) {
            float4 a4 = *(const float4*)&As[k][ty * 4];
            float4 b4 = *(const float4*)&Bs[k][tx * 4];
            float ar[4] = {a4.x, a4.y, a4.z, a4.w};
            float br[4] = {b4.x, b4.y, b4.z, b4.w};
#pragma unroll
            for (int i = 0; i < 4; i++)
#pragma unroll
                for (int j = 0; j < 4; j++) acc[i][j] += ar[i] * br[j];
        }
        __syncthreads();
    }

#pragma unroll
    for (int i = 0; i < 4; i++) {
        int m = m0 + ty * 4 + i;
#pragma unroll
        for (int j = 0; j < 4; j++) {
            int a = n0 + tx * 4 + j;
            float bias = isPL ? g_posW[(m % HLv) * ATTv + a] : g_t0[a];
            C[m * ATTv + a] = acc[i][j] + bias;
        }
    }
}

// ---------------- K3: logits + softmax + output GEMM ----------------
// One CTA per (b, chunk of 8 n's). PL[b] lives in dynamic smem (51 KB).
#define N_PER_CTA 8
#define SMEM_FLOATS (HLv * ATTv + ATTv + ATTv + N_PER_CTA * HLv + 64)

__global__ __launch_bounds__(256) void attn_kernel(const float* __restrict__ logv,
                                                   const int*   __restrict__ mask,
                                                   const float* __restrict__ pos_emb,
                                                   const float* __restrict__ W2,
                                                   const float* __restrict__ b2,
                                                   float* __restrict__ out) {
    const int b = blockIdx.y;
    const int nbase = blockIdx.x * N_PER_CTA;

    extern __shared__ __align__(16) float sm[];
    float* plS    = sm;                       // 50*256
    float* pnS    = plS + HLv * ATTv;         // 256
    float* w2S    = pnS + ATTv;               // 256
    float* attnS  = w2S + ATTv;               // 8*50
    float* logitS = attnS + N_PER_CTA * HLv;  // 50 (+pad)
    __shared__ int maskS[HLv];

    const int tid = threadIdx.x;

    // load PL[b] (coalesced float4)
    {
        const float4* src = (const float4*)(g_PL + b * HLv * ATTv);
        float4* dst = (float4*)plS;
        for (int i = tid; i < HLv * ATTv / 4; i += 256) dst[i] = src[i];
    }
    w2S[tid] = W2[tid];
    if (tid < HLv) maskS[tid] = mask[b * HLv + tid];
    __syncthreads();

    const float b2v = b2[0];
    const int w = tid >> 5, lane = tid & 31;

    for (int nl = 0; nl < N_PER_CTA; nl++) {
        // PN row for this n
        if (tid < ATTv / 4)
            ((float4*)pnS)[tid] = ((const float4*)(g_PN + (b * NNv + nbase + nl) * ATTv))[tid];
        __syncthreads();

        // logits: warps over h, lanes over a; skip tanh for masked h
        for (int h = w; h < HLv; h += 8) {
            float lg = -1e9f;
            if (maskS[h] != 0) {
                float s = 0.f;
                const float* pl = plS + h * ATTv;
#pragma unroll
                for (int i = 0; i < 8; i++) {
                    int a = lane + 32 * i;
                    s += w2S[a] * tanh_fast(pnS[a] + pl[a]);
                }
#pragma unroll
                for (int o = 16; o > 0; o >>= 1) s += __shfl_xor_sync(0xffffffffu, s, o);
                lg = s + b2v;
            }
            if (lane == 0) logitS[h] = lg;
        }
        __syncthreads();

        // softmax over 50 h (warp 0). All-masked -> uniform 1/50, matching jax.
        if (tid < 32) {
            float v0 = logitS[tid];
            float v1 = (tid + 32 < HLv) ? logitS[tid + 32] : -1e30f;
            float mx = fmaxf(v0, v1);
#pragma unroll
            for (int o = 16; o > 0; o >>= 1) mx = fmaxf(mx, __shfl_xor_sync(0xffffffffu, mx, o));
            float e0 = __expf(v0 - mx);
            float e1 = (tid + 32 < HLv) ? __expf(v1 - mx) : 0.f;
            float ssum = e0 + e1;
#pragma unroll
            for (int o = 16; o > 0; o >>= 1) ssum += __shfl_xor_sync(0xffffffffu, ssum, o);
            float inv = 1.f / ssum;
            attnS[nl * HLv + tid] = e0 * inv;
            if (tid + 32 < HLv) attnS[nl * HLv + tid + 32] = e1 * inv;
        }
        __syncthreads();
    }

    // output: out[b, nbase+j, d] = sum_h attn[j,h] * lf[b,h,d]
    // lf[b,h,d] = d<384 ? log_vec[b,h,d] : pos_emb[1+h, d-384]  (never materialized)
    for (int d = tid; d < NEWSv; d += 256) {
        float acc[N_PER_CTA];
#pragma unroll
        for (int j = 0; j < N_PER_CTA; j++) acc[j] = 0.f;

        if (d < INv) {
            const float* lp = logv + (size_t)b * HLv * INv + d;
#pragma unroll 2
            for (int h = 0; h < HLv; h++) {
                float lv = lp[h * INv];
#pragma unroll
                for (int j = 0; j < N_PER_CTA; j++) acc[j] += attnS[j * HLv + h] * lv;
            }
        } else {
            const float* pp = pos_emb + POSv + (d - INv);
#pragma unroll 2
            for (int h = 0; h < HLv; h++) {
                float lv = pp[h * POSv];
#pragma unroll
                for (int j = 0; j < N_PER_CTA; j++) acc[j] += attnS[j * HLv + h] * lv;
            }
        }
#pragma unroll
        for (int j = 0; j < N_PER_CTA; j++)
            out[(size_t)(b * NNv + nbase + j) * NEWSv + d] = acc[j];
    }
}

// ---------------- launch ----------------
extern "C" void kernel_launch(void* const* d_in, const int* in_sizes, int n_in,
                              void* d_out, int out_size) {
    const float* logv = (const float*)d_in[0];   // [64,50,384]
    const int*   mask = (const int*)  d_in[1];   // [64,50]
    const float* news = (const float*)d_in[2];   // [64,64,384]
    const float* pos  = (const float*)d_in[3];   // [100,64]
    const float* W1   = (const float*)d_in[4];   // [256,896]
    const float* b1   = (const float*)d_in[5];   // [256]
    const float* W2   = (const float*)d_in[6];   // [1,256]
    const float* b2   = (const float*)d_in[7];   // [1]

    float* out_user = (float*)d_out;                       // [64,64,448]
    float* out_nf   = out_user + (size_t)BB * NNv * NEWSv; // [64,64,448]

    cudaFuncSetAttribute(attn_kernel, cudaFuncAttributeMaxDynamicSharedMemorySize,
                         SMEM_FLOATS * 4);

    prep_kernel<<<51, 256>>>(pos, W1, b1);
    nf_kernel<<<BB * NNv, NEWSv>>>(news, pos, out_nf);
    gemm_kernel<<<dim3(4, 64, 2), 256>>>(news, logv, W1);
    attn_kernel<<<dim3(NNv / N_PER_CTA, BB), 256, SMEM_FLOATS * 4>>>(
        logv, mask, pos, W2, b2, out_user);
}

// round 5
// speedup vs baseline: 1.1548x; 1.1548x over previous
#include <cuda_runtime.h>

// ---------------- problem constants ----------------
#define BB    64    // batch
#define NNv   64    // news per batch
#define HLv   50    // history length
#define INv   384   // input dim
#define POSv  64    // pos-emb dim
#define ATTv  256   // attention hidden dim
#define NEWSv 448   // IN + POS
#define W1LD  896   // W1 row stride (2*NEWS)

// ---------------- device scratch (no allocations allowed) ----------------
__device__ float g_PN[BB * NNv * ATTv];    // 4 MB  : pn + t0   [4096, 256]
__device__ float g_PL[BB * HLv * ATTv];    // 3.3 MB: pl + posW [3200, 256]
__device__ float g_t0[ATTv];               // b1 + pos0 @ Wn_pos
__device__ float g_posW[HLv * ATTv];       // pos_emb[1+h] @ Wl_pos

__device__ __forceinline__ float tanh_fast(float x) {
    float y;
    asm("tanh.approx.f32 %0, %1;" : "=f"(y) : "f"(x));
    return y;
}

// ---------------- K0: tiny precompute of t0 and posW ----------------
__global__ void prep_kernel(const float* __restrict__ pos_emb,
                            const float* __restrict__ W1,
                            const float* __restrict__ b1) {
    int a = threadIdx.x;  // 0..255
    if (blockIdx.x == 0) {
        float s = b1[a];
#pragma unroll
        for (int j = 0; j < POSv; j++)
            s += pos_emb[j] * W1[a * W1LD + INv + j];
        g_t0[a] = s;
    } else {
        int h = blockIdx.x - 1;  // 0..49
        float s = 0.f;
#pragma unroll
        for (int j = 0; j < POSv; j++)
            s += pos_emb[(1 + h) * POSv + j] * W1[a * W1LD + NEWSv + INv + j];
        g_posW[h * ATTv + a] = s;
    }
}

// ---------------- K1: nf output (pure copy/broadcast, float4) ----------------
__global__ void nf_kernel(const float4* __restrict__ news4,
                          const float4* __restrict__ pos4,
                          float4* __restrict__ out4) {
    int bn = blockIdx.x;      // 0..4095
    int d4 = threadIdx.x;     // 0..111  (112 float4 = 448 floats)
    if (d4 >= NEWSv / 4) return;
    float4 v = (d4 < INv / 4) ? news4[bn * (INv / 4) + d4] : pos4[d4 - INv / 4];
    out4[bn * (NEWSv / 4) + d4] = v;
}

// ---------------- K2: fused FFMA GEMMs  (z=0: PN, z=1: PL) ----------------
// C[m,a] = sum_k A[m,k] * W1[a, colofs+k]  + bias
// Tiles: BM=BN=64, BK=16, 256 threads, 4x4 register blocking.
__global__ __launch_bounds__(256) void gemm_kernel(const float* __restrict__ news,
                                                   const float* __restrict__ logv,
                                                   const float* __restrict__ W1) {
    const int isPL = blockIdx.z;
    const float* A;
    float* C;
    int colofs;
    if (isPL) {
        if (blockIdx.y >= 50) return;  // PL has only 3200/64 = 50 row-blocks
        A = logv; C = g_PL; colofs = NEWSv;
    } else {
        A = news; C = g_PN; colofs = 0;
    }
    const int m0 = blockIdx.y * 64;
    const int n0 = blockIdx.x * 64;

    __shared__ __align__(16) float As[16][68];  // transposed: As[k][m]
    __shared__ __align__(16) float Bs[16][68];  // transposed: Bs[k][a]

    const int tid = threadIdx.x;
    const int tx = tid & 15, ty = tid >> 4;
    const int lr = tid >> 2, lc = tid & 3;   // loader: row, 4-float col group

    float acc[4][4];
#pragma unroll
    for (int i = 0; i < 4; i++)
#pragma unroll
        for (int j = 0; j < 4; j++) acc[i][j] = 0.f;

    const float* Aptr = A  + (m0 + lr) * INv  + lc * 4;
    const float* Bptr = W1 + (n0 + lr) * W1LD + colofs + lc * 4;

    for (int k0 = 0; k0 < INv; k0 += 16) {
        float4 av = *(const float4*)(Aptr + k0);
        float4 bv = *(const float4*)(Bptr + k0);
        As[lc * 4 + 0][lr] = av.x; As[lc * 4 + 1][lr] = av.y;
        As[lc * 4 + 2][lr] = av.z; As[lc * 4 + 3][lr] = av.w;
        Bs[lc * 4 + 0][lr] = bv.x; Bs[lc * 4 + 1][lr] = bv.y;
        Bs[lc * 4 + 2][lr] = bv.z; Bs[lc * 4 + 3][lr] = bv.w;
        __syncthreads();
#pragma unroll
        for (int k = 0; k < 16; k++) {
            float4 a4 = *(const float4*)&As[k][ty * 4];
            float4 b4 = *(const float4*)&Bs[k][tx * 4];
            float ar[4] = {a4.x, a4.y, a4.z, a4.w};
            float br[4] = {b4.x, b4.y, b4.z, b4.w};
#pragma unroll
            for (int i = 0; i < 4; i++)
#pragma unroll
                for (int j = 0; j < 4; j++) acc[i][j] += ar[i] * br[j];
        }
        __syncthreads();
    }

#pragma unroll
    for (int i = 0; i < 4; i++) {
        int m = m0 + ty * 4 + i;
#pragma unroll
        for (int j = 0; j < 4; j++) {
            int a = n0 + tx * 4 + j;
            float bias = isPL ? g_posW[(m % HLv) * ATTv + a] : g_t0[a];
            C[m * ATTv + a] = acc[i][j] + bias;
        }
    }
}

// ---------------- K3: logits + softmax + output GEMM (register-resident) ----
// One CTA per (b, 8 n's). pl/W2 live in registers; only pn tile in smem.
#define N_PER_CTA 8

__global__ __launch_bounds__(256) void attn_kernel(const float* __restrict__ logv,
                                                   const int*   __restrict__ mask,
                                                   const float* __restrict__ pos_emb,
                                                   const float* __restrict__ W2,
                                                   const float* __restrict__ b2,
                                                   float* __restrict__ out) {
    const int b = blockIdx.y;
    const int nbase = blockIdx.x * N_PER_CTA;

    __shared__ __align__(16) float pnS[N_PER_CTA][ATTv];   // 8 KB
    __shared__ float attnS[N_PER_CTA][HLv];                // logits -> attn
    __shared__ int maskS[HLv];

    const int tid = threadIdx.x;
    const int w = tid >> 5, lane = tid & 31;

    // pn tile: 8 rows x 256 = 512 float4, 2 per thread
    {
        const float4* src = (const float4*)(g_PN + (size_t)(b * NNv + nbase) * ATTv);
        float4* dst = (float4*)&pnS[0][0];
        dst[tid]       = src[tid];
        dst[tid + 256] = src[tid + 256];
    }
    if (tid < HLv) maskS[tid] = mask[b * HLv + tid];

    // W2 into registers (strided per lane, L1-cached broadcast across warps)
    float w2r[8];
#pragma unroll
    for (int i = 0; i < 8; i++) w2r[i] = W2[lane + 32 * i];
    const float b2v = b2[0];
    __syncthreads();

    // ---- logits: warp w handles h = w, w+8, ... ----
    for (int h = w; h < HLv; h += 8) {
        if (maskS[h] != 0) {
            const float* pl = g_PL + (size_t)(b * HLv + h) * ATTv;
            float plr[8];
#pragma unroll
            for (int i = 0; i < 8; i++) plr[i] = pl[lane + 32 * i];  // coalesced

            float s[N_PER_CTA];
#pragma unroll
            for (int n = 0; n < N_PER_CTA; n++) s[n] = 0.f;

#pragma unroll
            for (int i = 0; i < 8; i++) {
                const float pv = plr[i];
                const float wv = w2r[i];
                const int a = lane + 32 * i;
#pragma unroll
                for (int n = 0; n < N_PER_CTA; n++)
                    s[n] += wv * tanh_fast(pv + pnS[n][a]);
            }
#pragma unroll
            for (int n = 0; n < N_PER_CTA; n++) {
                float v = s[n];
#pragma unroll
                for (int o = 16; o > 0; o >>= 1) v += __shfl_xor_sync(0xffffffffu, v, o);
                if (lane == 0) attnS[n][h] = v + b2v;
            }
        } else {
            if (lane < N_PER_CTA) attnS[lane][h] = -1e9f;
        }
    }
    __syncthreads();

    // ---- softmax: warp w handles n = w (all 8 in parallel) ----
    {
        float v0 = attnS[w][lane];
        bool has1 = (lane + 32) < HLv;
        float v1 = has1 ? attnS[w][lane + 32] : -1e30f;
        float mx = fmaxf(v0, v1);
#pragma unroll
        for (int o = 16; o > 0; o >>= 1) mx = fmaxf(mx, __shfl_xor_sync(0xffffffffu, mx, o));
        float e0 = __expf(v0 - mx);
        float e1 = has1 ? __expf(v1 - mx) : 0.f;
        float ssum = e0 + e1;
#pragma unroll
        for (int o = 16; o > 0; o >>= 1) ssum += __shfl_xor_sync(0xffffffffu, ssum, o);
        float inv = 1.f / ssum;
        attnS[w][lane] = e0 * inv;
        if (has1) attnS[w][lane + 32] = e1 * inv;
    }
    __syncthreads();

    // ---- output: out[b, nbase+j, d] = sum_h attn[j,h] * lf[b,h,d] ----
    // lf[b,h,d] = d<384 ? log_vec[b,h,d] : pos_emb[1+h, d-384] (never materialized)
    for (int d = tid; d < NEWSv; d += 256) {
        float acc[N_PER_CTA];
#pragma unroll
        for (int j = 0; j < N_PER_CTA; j++) acc[j] = 0.f;

        if (d < INv) {
            const float* lp = logv + (size_t)b * HLv * INv + d;
#pragma unroll 2
            for (int h = 0; h < HLv; h++) {
                float lv = lp[h * INv];
#pragma unroll
                for (int j = 0; j < N_PER_CTA; j++) acc[j] += attnS[j][h] * lv;
            }
        } else {
            const float* pp = pos_emb + POSv + (d - INv);
#pragma unroll 2
            for (int h = 0; h < HLv; h++) {
                float lv = pp[h * POSv];
#pragma unroll
                for (int j = 0; j < N_PER_CTA; j++) acc[j] += attnS[j][h] * lv;
            }
        }
#pragma unroll
        for (int j = 0; j < N_PER_CTA; j++)
            out[(size_t)(b * NNv + nbase + j) * NEWSv + d] = acc[j];
    }
}

// ---------------- launch ----------------
extern "C" void kernel_launch(void* const* d_in, const int* in_sizes, int n_in,
                              void* d_out, int out_size) {
    const float* logv = (const float*)d_in[0];   // [64,50,384]
    const int*   mask = (const int*)  d_in[1];   // [64,50]
    const float* news = (const float*)d_in[2];   // [64,64,384]
    const float* pos  = (const float*)d_in[3];   // [100,64]
    const float* W1   = (const float*)d_in[4];   // [256,896]
    const float* b1   = (const float*)d_in[5];   // [256]
    const float* W2   = (const float*)d_in[6];   // [1,256]
    const float* b2   = (const float*)d_in[7];   // [1]

    float* out_user = (float*)d_out;                       // [64,64,448]
    float* out_nf   = out_user + (size_t)BB * NNv * NEWSv; // [64,64,448]

    prep_kernel<<<51, 256>>>(pos, W1, b1);
    nf_kernel<<<BB * NNv, 128>>>((const float4*)news, (const float4*)pos,
                                 (float4*)out_nf);
    gemm_kernel<<<dim3(4, 64, 2), 256>>>(news, logv, W1);
    attn_kernel<<<dim3(NNv / N_PER_CTA, BB), 256>>>(logv, mask, pos, W2, b2, out_user);
}